// round 8
// baseline (speedup 1.0000x reference)
#include <cuda_runtime.h>
#include <cuda_bf16.h>
#include <cstdint>

// Problem dims
#define BB   64
#define SS   196
#define EE   512
#define HH   512
#define AA   256
#define DD   512
#define VV   32000
#define LL   32
#define LM1  31
#define PADI 2

// ---------------- scratch (device globals; no runtime allocation) ----------
__device__ float g_enc_proj[BB * SS * AA];        // (b*S+s, A)
__device__ float g_h0buf[BB * HH];
__device__ float g_h1buf[BB * HH];
__device__ float g_Hbuf[LM1 * BB * HH];           // (t*B+b, H)
__device__ float g_dec[BB * AA];
__device__ float g_sc[BB * SS];
__device__ float g_ctx[BB * EE];
__device__ float g_Xemb[LM1 * BB * DD];           // gathered embeddings
__device__ float g_giE[LM1 * BB * 3 * HH];        // emb part of gi (+b_ih)
__device__ float g_gg[BB * 3072];                 // [GC(1536) | GH(1536)] per b

// ---------------- helpers ----------------
__device__ __forceinline__ float ftanh(float x) {
    float e = __expf(2.0f * x);
    return 1.0f - __fdividef(2.0f, e + 1.0f);
}
__device__ __forceinline__ float fsig(float x) {
    return __fdividef(1.0f, 1.0f + __expf(-x));
}
__device__ __forceinline__ float warp_sum(float v) {
    #pragma unroll
    for (int o = 16; o; o >>= 1) v += __shfl_xor_sync(0xffffffffu, v, o);
    return v;
}

// ---------------- generic tiled fp32 GEMM:  C = A(MxK) * B(NxK)^T + bias ----
// MODE 0: C[m*N+n] = v ; MODE 1: C[m*N+n] = tanh(v) ; MODE 2: out remap (b,t,v)
#define TBM 128
#define TBN 128
#define TBK 16

template<int MODE>
__global__ __launch_bounds__(256)
void gemm_tn(const float* __restrict__ Ag, const float* __restrict__ Bg,
             float* __restrict__ Cg, int M, int N, int K, int ldb,
             const float* __restrict__ bias)
{
    __shared__ float As[TBK][TBM + 4];
    __shared__ float Bs[TBK][TBN + 4];
    const int tid = threadIdx.x;
    const int tx = tid & 15, ty = tid >> 4;
    const int bm = blockIdx.y * TBM, bn = blockIdx.x * TBN;

    float acc[8][8];
    #pragma unroll
    for (int i = 0; i < 8; i++)
        #pragma unroll
        for (int j = 0; j < 8; j++) acc[i][j] = 0.0f;

    for (int k0 = 0; k0 < K; k0 += TBK) {
        #pragma unroll
        for (int i = 0; i < 2; i++) {
            int lin = tid + i * 256;       // 512 float4 slots (128 rows x 4 quads)
            int row = lin >> 2, kq = lin & 3;
            int gm = bm + row;
            float4 v = make_float4(0.f, 0.f, 0.f, 0.f);
            if (gm < M) v = *(const float4*)(Ag + (size_t)gm * K + k0 + kq * 4);
            As[kq * 4 + 0][row] = v.x; As[kq * 4 + 1][row] = v.y;
            As[kq * 4 + 2][row] = v.z; As[kq * 4 + 3][row] = v.w;
        }
        #pragma unroll
        for (int i = 0; i < 2; i++) {
            int lin = tid + i * 256;
            int row = lin >> 2, kq = lin & 3;
            int gn = bn + row;
            float4 v = make_float4(0.f, 0.f, 0.f, 0.f);
            if (gn < N) v = *(const float4*)(Bg + (size_t)gn * ldb + k0 + kq * 4);
            Bs[kq * 4 + 0][row] = v.x; Bs[kq * 4 + 1][row] = v.y;
            Bs[kq * 4 + 2][row] = v.z; Bs[kq * 4 + 3][row] = v.w;
        }
        __syncthreads();
        #pragma unroll
        for (int k = 0; k < TBK; k++) {
            float a[8], b[8];
            #pragma unroll
            for (int i = 0; i < 8; i++) a[i] = As[k][ty * 8 + i];
            #pragma unroll
            for (int j = 0; j < 8; j++) b[j] = Bs[k][tx * 8 + j];
            #pragma unroll
            for (int i = 0; i < 8; i++)
                #pragma unroll
                for (int j = 0; j < 8; j++) acc[i][j] += a[i] * b[j];
        }
        __syncthreads();
    }

    #pragma unroll
    for (int i = 0; i < 8; i++) {
        int gm = bm + ty * 8 + i;
        if (gm >= M) continue;
        #pragma unroll
        for (int j = 0; j < 8; j++) {
            int gn = bn + tx * 8 + j;
            if (gn >= N) continue;
            float v = acc[i][j] + bias[gn];
            if (MODE == 0) {
                Cg[(size_t)gm * N + gn] = v;
            } else if (MODE == 1) {
                Cg[(size_t)gm * N + gn] = ftanh(v);
            } else {
                int t = gm >> 6, b = gm & 63;   // m = t*64+b
                Cg[((size_t)(b * LM1 + t)) * N + gn] = v;
            }
        }
    }
}

// ---------------- gather teacher-forced embeddings ----------------
// NOTE: targets are int32 on-device (JAX x64 disabled downcasts the int64
// request). Reading them as int64 was the round-6 illegal-access bug.
__global__ void k_gather(const int* __restrict__ tg,
                         const float* __restrict__ emb,
                         float* __restrict__ X)
{
    int m = blockIdx.x;            // t*64 + b
    int t = m >> 6, b = m & 63;
    int tok = tg[b * LL + t];
    float4 v;
    if (tok == PADI || tok < 0 || tok >= VV)
        v = make_float4(0.f, 0.f, 0.f, 0.f);
    else
        v = ((const float4*)(emb + (size_t)tok * DD))[threadIdx.x];
    ((float4*)(X + (size_t)m * DD))[threadIdx.x] = v;
}

// ---------------- dec_proj: (B,A) = h @ W_dec^T + b_dec (warp per output) ---
__global__ void k_decproj(const float* __restrict__ h, const float* __restrict__ Wdec,
                          const float* __restrict__ bdec, float* __restrict__ out)
{
    int w = blockIdx.x * 8 + (threadIdx.x >> 5);
    int lane = threadIdx.x & 31;
    int b = w >> 8, n = w & 255;
    const float4* h4 = (const float4*)(h + b * HH);
    const float4* w4 = (const float4*)(Wdec + (size_t)n * HH);
    float acc = 0.f;
    #pragma unroll
    for (int i = 0; i < 4; i++) {
        float4 a = h4[lane + 32 * i], c = w4[lane + 32 * i];
        acc += a.x * c.x + a.y * c.y + a.z * c.z + a.w * c.w;
    }
    acc = warp_sum(acc);
    if (lane == 0) out[b * 256 + n] = acc + bdec[n];
}

// ---------------- energy + score reduction (warp per (b,s)) ----------------
__global__ void k_energy(const float* __restrict__ ep, const float* __restrict__ dp,
                         const float* __restrict__ ws, const float* __restrict__ bsc,
                         float* __restrict__ scores)
{
    int w = blockIdx.x * 8 + (threadIdx.x >> 5);   // (b*S+s), 12544 total
    int lane = threadIdx.x & 31;
    int b = w / SS;
    const float4* e4 = (const float4*)(ep + (size_t)w * AA);
    const float4* d4 = (const float4*)(dp + b * AA);
    const float4* s4 = (const float4*)ws;
    float acc = 0.f;
    #pragma unroll
    for (int i = 0; i < 2; i++) {
        float4 e = e4[lane + 32 * i], d = d4[lane + 32 * i], s = s4[lane + 32 * i];
        acc += ftanh(e.x + d.x) * s.x + ftanh(e.y + d.y) * s.y
             + ftanh(e.z + d.z) * s.z + ftanh(e.w + d.w) * s.w;
    }
    acc = warp_sum(acc);
    if (lane == 0) scores[w] = acc + bsc[0];
}

// ---------------- softmax over S + context = weights @ encoder_out ---------
__global__ void k_softctx(const float* __restrict__ scores, const float* __restrict__ eo,
                          float* __restrict__ ctx)
{
    __shared__ float w[SS];
    __shared__ float red[8];
    int b = blockIdx.x, tid = threadIdx.x;
    int lane = tid & 31, wid = tid >> 5;

    float sc = (tid < SS) ? scores[b * SS + tid] : -1e30f;
    float m = sc;
    #pragma unroll
    for (int o = 16; o; o >>= 1) m = fmaxf(m, __shfl_xor_sync(0xffffffffu, m, o));
    if (lane == 0) red[wid] = m;
    __syncthreads();
    float mx = red[0];
    #pragma unroll
    for (int i = 1; i < 8; i++) mx = fmaxf(mx, red[i]);

    float ex = (tid < SS) ? __expf(sc - mx) : 0.f;
    float s = ex;
    #pragma unroll
    for (int o = 16; o; o >>= 1) s += __shfl_xor_sync(0xffffffffu, s, o);
    __syncthreads();               // done reading red(max)
    if (lane == 0) red[wid] = s;
    __syncthreads();
    float tot = 0.f;
    #pragma unroll
    for (int i = 0; i < 8; i++) tot += red[i];
    if (tid < SS) w[tid] = ex / tot;
    __syncthreads();

    const float* eb = eo + (size_t)b * SS * EE;
    for (int e = tid; e < EE; e += 256) {
        float a0 = 0.f, a1 = 0.f, a2 = 0.f, a3 = 0.f;
        #pragma unroll 4
        for (int s2 = 0; s2 < SS; s2 += 4) {      // 196 = 49*4
            a0 += w[s2 + 0] * eb[(s2 + 0) * EE + e];
            a1 += w[s2 + 1] * eb[(s2 + 1) * EE + e];
            a2 += w[s2 + 2] * eb[(s2 + 2) * EE + e];
            a3 += w[s2 + 3] * eb[(s2 + 3) * EE + e];
        }
        ctx[b * EE + e] = (a0 + a1) + (a2 + a3);
    }
}

// -------- per-step GEMM: [GC | GH] = [ctx|h](64x512) @ [W_ihE;W_hh]^T ------
// grid 96 blocks: n0 = blockIdx.x*32 over N_total = 3072. BM=64, BN=32, BK=16.
__global__ __launch_bounds__(256)
void k_gcgh(const float* __restrict__ ctx, const float* __restrict__ h,
            const float* __restrict__ Wih, const float* __restrict__ Whh,
            float* __restrict__ gg)
{
    __shared__ float As[16][68];
    __shared__ float Bs[32][17];
    const int tid = threadIdx.x;
    const int lane = tid & 31, wid = tid >> 5;   // lane = n-within-tile, wid = m-group
    const int n0 = blockIdx.x * 32;

    const float* Am; const float* Bm; int ldbm; int nrow0;
    if (n0 < 1536) { Am = ctx; Bm = Wih + DD; ldbm = DD + EE; nrow0 = n0; }
    else           { Am = h;   Bm = Whh;      ldbm = HH;      nrow0 = n0 - 1536; }

    float acc[8];
    #pragma unroll
    for (int j = 0; j < 8; j++) acc[j] = 0.f;

    for (int k0 = 0; k0 < 512; k0 += 16) {
        {   // A tile 64x16 = 256 float4, one per thread
            int row = tid >> 2, kq = tid & 3;
            float4 v = *(const float4*)(Am + row * 512 + k0 + kq * 4);
            As[kq * 4 + 0][row] = v.x; As[kq * 4 + 1][row] = v.y;
            As[kq * 4 + 2][row] = v.z; As[kq * 4 + 3][row] = v.w;
        }
        #pragma unroll
        for (int i = 0; i < 2; i++) {   // B tile 32x16 = 512 floats
            int linb = tid + i * 256;
            int nl = linb >> 4, kk = linb & 15;
            Bs[nl][kk] = Bm[(size_t)(nrow0 + nl) * ldbm + k0 + kk];
        }
        __syncthreads();
        #pragma unroll
        for (int k = 0; k < 16; k++) {
            float bv = Bs[lane][k];
            float4 a0 = *(const float4*)&As[k][wid * 8];
            float4 a1 = *(const float4*)&As[k][wid * 8 + 4];
            acc[0] += a0.x * bv; acc[1] += a0.y * bv;
            acc[2] += a0.z * bv; acc[3] += a0.w * bv;
            acc[4] += a1.x * bv; acc[5] += a1.y * bv;
            acc[6] += a1.z * bv; acc[7] += a1.w * bv;
        }
        __syncthreads();
    }
    #pragma unroll
    for (int j = 0; j < 8; j++)
        gg[(wid * 8 + j) * 3072 + n0 + lane] = acc[j];
}

// ---------------- GRU gate combine + hidden update ----------------
__global__ void k_gate(const float* __restrict__ gg, const float* __restrict__ giE,
                       const float* __restrict__ bhh, const float* __restrict__ hold,
                       float* __restrict__ hnew, float* __restrict__ Hbuf, int t)
{
    int idx = blockIdx.x * 256 + threadIdx.x;    // < 32768
    int b = idx >> 9, k = idx & 511;
    const float* g = gg + b * 3072;
    size_t mi = (size_t)(t * BB + b) * 1536;
    float r = fsig(giE[mi + k]        + g[k]        + g[1536 + k]        + bhh[k]);
    float z = fsig(giE[mi + 512 + k]  + g[512 + k]  + g[1536 + 512 + k]  + bhh[512 + k]);
    float n = ftanh(giE[mi + 1024 + k] + g[1024 + k]
                    + r * (g[1536 + 1024 + k] + bhh[1024 + k]));
    float ho = hold[idx];
    float hn = (1.f - z) * n + z * ho;
    hnew[idx] = hn;
    Hbuf[(size_t)(t * BB + b) * HH + k] = hn;
}

// ---------------- host driver ----------------
extern "C" void kernel_launch(void* const* d_in, const int* in_sizes, int n_in,
                              void* d_out, int out_size)
{
    const float* enc     = (const float*)d_in[0];
    const float* pooled  = (const float*)d_in[1];
    const int*   targets = (const int*)d_in[2];     // int32 on device (JAX x64 off)
    const float* emb     = (const float*)d_in[3];
    const float* W_enc   = (const float*)d_in[4];
    const float* b_enc   = (const float*)d_in[5];
    const float* W_dec   = (const float*)d_in[6];
    const float* b_dec   = (const float*)d_in[7];
    const float* W_score = (const float*)d_in[8];
    const float* b_score = (const float*)d_in[9];
    const float* W_ih    = (const float*)d_in[10];
    const float* W_hh    = (const float*)d_in[11];
    const float* b_ih    = (const float*)d_in[12];
    const float* b_hh    = (const float*)d_in[13];
    const float* W_out   = (const float*)d_in[14];
    const float* b_out   = (const float*)d_in[15];
    const float* W_init  = (const float*)d_in[16];
    const float* b_init  = (const float*)d_in[17];
    float* out = (float*)d_out;

    float *p_ep, *p_h0, *p_h1, *p_Hb, *p_dec, *p_sc, *p_ctx, *p_X, *p_giE, *p_gg;
    cudaGetSymbolAddress((void**)&p_ep,  g_enc_proj);
    cudaGetSymbolAddress((void**)&p_h0,  g_h0buf);
    cudaGetSymbolAddress((void**)&p_h1,  g_h1buf);
    cudaGetSymbolAddress((void**)&p_Hb,  g_Hbuf);
    cudaGetSymbolAddress((void**)&p_dec, g_dec);
    cudaGetSymbolAddress((void**)&p_sc,  g_sc);
    cudaGetSymbolAddress((void**)&p_ctx, g_ctx);
    cudaGetSymbolAddress((void**)&p_X,   g_Xemb);
    cudaGetSymbolAddress((void**)&p_giE, g_giE);
    cudaGetSymbolAddress((void**)&p_gg,  g_gg);

    // h0 = tanh(pooled @ W_init^T + b_init)
    gemm_tn<1><<<dim3(4, 1), 256>>>(pooled, W_init, p_h0, BB, HH, EE, EE, b_init);
    // enc_proj = encoder_out @ W_enc^T + b_enc          (12544 x 256 x 512)
    gemm_tn<0><<<dim3(2, 98), 256>>>(enc, W_enc, p_ep, BB * SS, AA, EE, EE, b_enc);
    // gather embeddings for all teacher-forced tokens
    k_gather<<<LM1 * BB, 128>>>(targets, emb, p_X);
    // giE = Xemb @ W_ih[:, :D]^T + b_ih                 (1984 x 1536 x 512)
    gemm_tn<0><<<dim3(12, 16), 256>>>(p_X, W_ih, p_giE, LM1 * BB, 3 * HH, DD,
                                      DD + EE, b_ih);

    for (int t = 0; t < LM1; t++) {
        float* hcur = (t & 1) ? p_h1 : p_h0;
        float* hnxt = (t & 1) ? p_h0 : p_h1;
        k_decproj<<<2048, 256>>>(hcur, W_dec, b_dec, p_dec);
        k_energy<<<1568, 256>>>(p_ep, p_dec, W_score, b_score, p_sc);
        k_softctx<<<BB, 256>>>(p_sc, enc, p_ctx);
        k_gcgh<<<96, 256>>>(p_ctx, hcur, W_ih, W_hh, p_gg);
        k_gate<<<128, 256>>>(p_gg, p_giE, b_hh, hcur, hnxt, p_Hb, t);
    }

    // logits = Hbuf @ W_out^T + b_out -> out[b, t, v]   (1984 x 32000 x 512)
    gemm_tn<2><<<dim3(250, 16), 256>>>(p_Hb, W_out, out, LM1 * BB, VV, HH, HH, b_out);
}

// round 9
// speedup vs baseline: 1.3734x; 1.3734x over previous
#include <cuda_runtime.h>
#include <cuda_bf16.h>
#include <cstdint>

// Problem dims
#define BB   64
#define SS   196
#define EE   512
#define HH   512
#define AA   256
#define DD   512
#define VV   32000
#define LL   32
#define LM1  31
#define PADI 2
#define MM   (LM1 * BB)        // 1984
#define KP   1536              // 3 * 512 split-K for bf16x3 GEMM

// ---------------- scratch (device globals; no runtime allocation) ----------
__device__ float g_enc_proj[BB * SS * AA];        // (b*S+s, A)
__device__ float g_h0buf[BB * HH];
__device__ float g_h1buf[BB * HH];
__device__ float g_Hbuf[MM * HH];                 // (t*B+b, H)
__device__ float g_dec[BB * AA];
__device__ float g_sc[BB * SS];
__device__ float g_ctx[BB * EE];
__device__ float g_Xemb[MM * DD];                 // gathered embeddings
__device__ float g_giE[MM * 3 * HH];              // emb part of gi (+b_ih)
__device__ float g_gg[BB * 3072];                 // [GC(1536) | GH(1536)] per b
__device__ __nv_bfloat16 g_Ae[MM * KP];           // [Hhi | Hlo | Hhi]
__device__ __nv_bfloat16 g_Be[(size_t)VV * KP];   // [Whi | Whi | Wlo]  (~98 MB)

// ---------------- helpers ----------------
__device__ __forceinline__ float ftanh(float x) {
    float e = __expf(2.0f * x);
    return 1.0f - __fdividef(2.0f, e + 1.0f);
}
__device__ __forceinline__ float fsig(float x) {
    return __fdividef(1.0f, 1.0f + __expf(-x));
}
__device__ __forceinline__ float warp_sum(float v) {
    #pragma unroll
    for (int o = 16; o; o >>= 1) v += __shfl_xor_sync(0xffffffffu, v, o);
    return v;
}
__device__ __forceinline__ uint32_t smem_u32(const void* p) {
    return (uint32_t)__cvta_generic_to_shared(p);
}

// ---------------- generic tiled fp32 GEMM:  C = A(MxK) * B(NxK)^T + bias ----
// MODE 0: C[m*N+n] = v ; MODE 1: C[m*N+n] = tanh(v)
#define TBM 128
#define TBN 128
#define TBK 16

template<int MODE>
__global__ __launch_bounds__(256)
void gemm_tn(const float* __restrict__ Ag, const float* __restrict__ Bg,
             float* __restrict__ Cg, int M, int N, int K, int ldb,
             const float* __restrict__ bias)
{
    __shared__ float As[TBK][TBM + 4];
    __shared__ float Bs[TBK][TBN + 4];
    const int tid = threadIdx.x;
    const int tx = tid & 15, ty = tid >> 4;
    const int bm = blockIdx.y * TBM, bn = blockIdx.x * TBN;

    float acc[8][8];
    #pragma unroll
    for (int i = 0; i < 8; i++)
        #pragma unroll
        for (int j = 0; j < 8; j++) acc[i][j] = 0.0f;

    for (int k0 = 0; k0 < K; k0 += TBK) {
        #pragma unroll
        for (int i = 0; i < 2; i++) {
            int lin = tid + i * 256;
            int row = lin >> 2, kq = lin & 3;
            int gm = bm + row;
            float4 v = make_float4(0.f, 0.f, 0.f, 0.f);
            if (gm < M) v = *(const float4*)(Ag + (size_t)gm * K + k0 + kq * 4);
            As[kq * 4 + 0][row] = v.x; As[kq * 4 + 1][row] = v.y;
            As[kq * 4 + 2][row] = v.z; As[kq * 4 + 3][row] = v.w;
        }
        #pragma unroll
        for (int i = 0; i < 2; i++) {
            int lin = tid + i * 256;
            int row = lin >> 2, kq = lin & 3;
            int gn = bn + row;
            float4 v = make_float4(0.f, 0.f, 0.f, 0.f);
            if (gn < N) v = *(const float4*)(Bg + (size_t)gn * ldb + k0 + kq * 4);
            Bs[kq * 4 + 0][row] = v.x; Bs[kq * 4 + 1][row] = v.y;
            Bs[kq * 4 + 2][row] = v.z; Bs[kq * 4 + 3][row] = v.w;
        }
        __syncthreads();
        #pragma unroll
        for (int k = 0; k < TBK; k++) {
            float a[8], b[8];
            #pragma unroll
            for (int i = 0; i < 8; i++) a[i] = As[k][ty * 8 + i];
            #pragma unroll
            for (int j = 0; j < 8; j++) b[j] = Bs[k][tx * 8 + j];
            #pragma unroll
            for (int i = 0; i < 8; i++)
                #pragma unroll
                for (int j = 0; j < 8; j++) acc[i][j] += a[i] * b[j];
        }
        __syncthreads();
    }

    #pragma unroll
    for (int i = 0; i < 8; i++) {
        int gm = bm + ty * 8 + i;
        if (gm >= M) continue;
        #pragma unroll
        for (int j = 0; j < 8; j++) {
            int gn = bn + tx * 8 + j;
            if (gn >= N) continue;
            float v = acc[i][j] + bias[gn];
            if (MODE == 0) Cg[(size_t)gm * N + gn] = v;
            else           Cg[(size_t)gm * N + gn] = ftanh(v);
        }
    }
}

// ---------------- fp32 -> (hi, lo) bf16 split kernels ----------------------
// W_out (VV x 512) -> Be (VV x 1536) = [hi | hi | lo]
__global__ void k_splitW(const float* __restrict__ W, __nv_bfloat16* __restrict__ Be)
{
    int idx = blockIdx.x * 256 + threadIdx.x;    // over VV*128 float4 slots
    int n = idx >> 7, q = idx & 127;
    float4 v = *(const float4*)(W + (size_t)n * 512 + q * 4);
    __nv_bfloat16 h0 = __float2bfloat16_rn(v.x);
    __nv_bfloat16 h1 = __float2bfloat16_rn(v.y);
    __nv_bfloat16 h2 = __float2bfloat16_rn(v.z);
    __nv_bfloat16 h3 = __float2bfloat16_rn(v.w);
    __nv_bfloat16 l0 = __float2bfloat16_rn(v.x - __bfloat162float(h0));
    __nv_bfloat16 l1 = __float2bfloat16_rn(v.y - __bfloat162float(h1));
    __nv_bfloat16 l2 = __float2bfloat16_rn(v.z - __bfloat162float(h2));
    __nv_bfloat16 l3 = __float2bfloat16_rn(v.w - __bfloat162float(h3));
    __nv_bfloat162* p0 = (__nv_bfloat162*)(Be + (size_t)n * KP + q * 4);
    __nv_bfloat162* p1 = (__nv_bfloat162*)(Be + (size_t)n * KP + 512 + q * 4);
    __nv_bfloat162* p2 = (__nv_bfloat162*)(Be + (size_t)n * KP + 1024 + q * 4);
    p0[0] = __nv_bfloat162(h0, h1); p0[1] = __nv_bfloat162(h2, h3);
    p1[0] = __nv_bfloat162(h0, h1); p1[1] = __nv_bfloat162(h2, h3);
    p2[0] = __nv_bfloat162(l0, l1); p2[1] = __nv_bfloat162(l2, l3);
}

// Hbuf (MM x 512) -> Ae (MM x 1536) = [hi | lo | hi]
__global__ void k_splitA(const float* __restrict__ H, __nv_bfloat16* __restrict__ Ae)
{
    int idx = blockIdx.x * 256 + threadIdx.x;    // over MM*128 float4 slots
    int m = idx >> 7, q = idx & 127;
    float4 v = *(const float4*)(H + (size_t)m * 512 + q * 4);
    __nv_bfloat16 h0 = __float2bfloat16_rn(v.x);
    __nv_bfloat16 h1 = __float2bfloat16_rn(v.y);
    __nv_bfloat16 h2 = __float2bfloat16_rn(v.z);
    __nv_bfloat16 h3 = __float2bfloat16_rn(v.w);
    __nv_bfloat16 l0 = __float2bfloat16_rn(v.x - __bfloat162float(h0));
    __nv_bfloat16 l1 = __float2bfloat16_rn(v.y - __bfloat162float(h1));
    __nv_bfloat16 l2 = __float2bfloat16_rn(v.z - __bfloat162float(h2));
    __nv_bfloat16 l3 = __float2bfloat16_rn(v.w - __bfloat162float(h3));
    __nv_bfloat162* p0 = (__nv_bfloat162*)(Ae + (size_t)m * KP + q * 4);
    __nv_bfloat162* p1 = (__nv_bfloat162*)(Ae + (size_t)m * KP + 512 + q * 4);
    __nv_bfloat162* p2 = (__nv_bfloat162*)(Ae + (size_t)m * KP + 1024 + q * 4);
    p0[0] = __nv_bfloat162(h0, h1); p0[1] = __nv_bfloat162(h2, h3);
    p1[0] = __nv_bfloat162(l0, l1); p1[1] = __nv_bfloat162(l2, l3);
    p2[0] = __nv_bfloat162(h0, h1); p2[1] = __nv_bfloat162(h2, h3);
}

// ---------------- bf16 tensor-core output GEMM -----------------------------
// C(b,t,v) = Ae(MM x KP) @ Be(VV x KP)^T + b_out, fp32 accumulate.
// 128x128 block tile, BK=32, 8 warps (2m x 4n), m16n8k16 mma, cp.async 2-stage.
#define GBK 32
#define APAD 8
#define LDA (GBK + APAD)       // 40 bf16 per smem row

__global__ __launch_bounds__(256)
void k_bigmm(const __nv_bfloat16* __restrict__ Ae,
             const __nv_bfloat16* __restrict__ Be,
             const float* __restrict__ bias, float* __restrict__ out)
{
    __shared__ __align__(16) __nv_bfloat16 As[2][128][LDA];
    __shared__ __align__(16) __nv_bfloat16 Bs[2][128][LDA];

    const int tid  = threadIdx.x;
    const int lane = tid & 31, warp = tid >> 5;
    const int wm = (warp & 1) * 64;      // warp m-offset within tile
    const int wn = (warp >> 1) * 32;     // warp n-offset within tile
    const int bn = blockIdx.x * 128;     // 250 tiles, exact
    const int bm = blockIdx.y * 128;     // 16 tiles, last partial (M=1984)

    float c[4][4][4];
    #pragma unroll
    for (int i = 0; i < 4; i++)
        #pragma unroll
        for (int j = 0; j < 4; j++) {
            c[i][j][0] = 0.f; c[i][j][1] = 0.f; c[i][j][2] = 0.f; c[i][j][3] = 0.f;
        }

    const int lrow = tid >> 2, lq = tid & 3;    // load mapping: 2 chunks/thread

    // ---- async tile load for stage s at k-offset k0 ----
    auto load_tile = [&](int s, int k0) {
        #pragma unroll
        for (int i = 0; i < 2; i++) {
            int row = lrow + i * 64;
            int gm = bm + row;
            uint32_t da = smem_u32(&As[s][row][lq * 8]);
            const __nv_bfloat16* sa = Ae + (size_t)gm * KP + k0 + lq * 8;
            int szA = (gm < MM) ? 16 : 0;
            asm volatile("cp.async.cg.shared.global [%0], [%1], 16, %2;"
                         :: "r"(da), "l"(sa), "r"(szA));
            uint32_t db = smem_u32(&Bs[s][row][lq * 8]);
            const __nv_bfloat16* sb = Be + (size_t)(bn + row) * KP + k0 + lq * 8;
            asm volatile("cp.async.cg.shared.global [%0], [%1], 16;"
                         :: "r"(db), "l"(sb));
        }
    };

    load_tile(0, 0);
    asm volatile("cp.async.commit_group;");

    const int a_r = lane & 15, a_c = (lane >> 4) * 8;
    const int b_r = lane & 7,  b_c = ((lane >> 3) & 1) * 8;

    const int NIT = KP / GBK;   // 48
    for (int it = 0; it < NIT; it++) {
        int cur = it & 1;
        if (it + 1 < NIT) {
            load_tile((it + 1) & 1, (it + 1) * GBK);
            asm volatile("cp.async.commit_group;");
            asm volatile("cp.async.wait_group 1;");
        } else {
            asm volatile("cp.async.wait_group 0;");
        }
        __syncthreads();

        #pragma unroll
        for (int kh = 0; kh < 2; kh++) {
            uint32_t a[4][4], b[4][2];
            #pragma unroll
            for (int mi = 0; mi < 4; mi++) {
                uint32_t ad = smem_u32(&As[cur][wm + mi * 16 + a_r][kh * 16 + a_c]);
                asm volatile("ldmatrix.sync.aligned.m8n8.x4.shared.b16 "
                             "{%0,%1,%2,%3}, [%4];"
                             : "=r"(a[mi][0]), "=r"(a[mi][1]),
                               "=r"(a[mi][2]), "=r"(a[mi][3]) : "r"(ad));
            }
            #pragma unroll
            for (int ni = 0; ni < 4; ni++) {
                uint32_t bd = smem_u32(&Bs[cur][wn + ni * 8 + b_r][kh * 16 + b_c]);
                asm volatile("ldmatrix.sync.aligned.m8n8.x2.shared.b16 "
                             "{%0,%1}, [%2];"
                             : "=r"(b[ni][0]), "=r"(b[ni][1]) : "r"(bd));
            }
            #pragma unroll
            for (int mi = 0; mi < 4; mi++)
                #pragma unroll
                for (int ni = 0; ni < 4; ni++) {
                    asm volatile(
                        "mma.sync.aligned.m16n8k16.row.col.f32.bf16.bf16.f32 "
                        "{%0,%1,%2,%3}, {%4,%5,%6,%7}, {%8,%9}, {%0,%1,%2,%3};"
                        : "+f"(c[mi][ni][0]), "+f"(c[mi][ni][1]),
                          "+f"(c[mi][ni][2]), "+f"(c[mi][ni][3])
                        : "r"(a[mi][0]), "r"(a[mi][1]), "r"(a[mi][2]), "r"(a[mi][3]),
                          "r"(b[ni][0]), "r"(b[ni][1]));
                }
        }
        __syncthreads();
    }

    // ---- epilogue: bias + remap (t*64+b, v) -> out[(b*31+t)*V + v] ----
    const int er = lane >> 2, ec = (lane & 3) * 2;
    #pragma unroll
    for (int mi = 0; mi < 4; mi++) {
        int gm0 = bm + wm + mi * 16 + er;
        int gm1 = gm0 + 8;
        #pragma unroll
        for (int ni = 0; ni < 4; ni++) {
            int gn = bn + wn + ni * 8 + ec;
            float bv0 = bias[gn], bv1 = bias[gn + 1];
            if (gm0 < MM) {
                int t = gm0 >> 6, bb = gm0 & 63;
                float2* o = (float2*)(out + (size_t)(bb * LM1 + t) * VV + gn);
                *o = make_float2(c[mi][ni][0] + bv0, c[mi][ni][1] + bv1);
            }
            if (gm1 < MM) {
                int t = gm1 >> 6, bb = gm1 & 63;
                float2* o = (float2*)(out + (size_t)(bb * LM1 + t) * VV + gn);
                *o = make_float2(c[mi][ni][2] + bv0, c[mi][ni][3] + bv1);
            }
        }
    }
}

// ---------------- gather teacher-forced embeddings ----------------
__global__ void k_gather(const int* __restrict__ tg,
                         const float* __restrict__ emb,
                         float* __restrict__ X)
{
    int m = blockIdx.x;            // t*64 + b
    int t = m >> 6, b = m & 63;
    int tok = tg[b * LL + t];
    float4 v;
    if (tok == PADI || tok < 0 || tok >= VV)
        v = make_float4(0.f, 0.f, 0.f, 0.f);
    else
        v = ((const float4*)(emb + (size_t)tok * DD))[threadIdx.x];
    ((float4*)(X + (size_t)m * DD))[threadIdx.x] = v;
}

// ---------------- dec_proj: (B,A) = h @ W_dec^T + b_dec (warp per output) ---
__global__ void k_decproj(const float* __restrict__ h, const float* __restrict__ Wdec,
                          const float* __restrict__ bdec, float* __restrict__ out)
{
    int w = blockIdx.x * 8 + (threadIdx.x >> 5);
    int lane = threadIdx.x & 31;
    int b = w >> 8, n = w & 255;
    const float4* h4 = (const float4*)(h + b * HH);
    const float4* w4 = (const float4*)(Wdec + (size_t)n * HH);
    float acc = 0.f;
    #pragma unroll
    for (int i = 0; i < 4; i++) {
        float4 a = h4[lane + 32 * i], cc = w4[lane + 32 * i];
        acc += a.x * cc.x + a.y * cc.y + a.z * cc.z + a.w * cc.w;
    }
    acc = warp_sum(acc);
    if (lane == 0) out[b * 256 + n] = acc + bdec[n];
}

// ---------------- energy + score reduction (warp per (b,s)) ----------------
__global__ void k_energy(const float* __restrict__ ep, const float* __restrict__ dp,
                         const float* __restrict__ ws, const float* __restrict__ bsc,
                         float* __restrict__ scores)
{
    int w = blockIdx.x * 8 + (threadIdx.x >> 5);   // (b*S+s), 12544 total
    int lane = threadIdx.x & 31;
    int b = w / SS;
    const float4* e4 = (const float4*)(ep + (size_t)w * AA);
    const float4* d4 = (const float4*)(dp + b * AA);
    const float4* s4 = (const float4*)ws;
    float acc = 0.f;
    #pragma unroll
    for (int i = 0; i < 2; i++) {
        float4 e = e4[lane + 32 * i], d = d4[lane + 32 * i], s = s4[lane + 32 * i];
        acc += ftanh(e.x + d.x) * s.x + ftanh(e.y + d.y) * s.y
             + ftanh(e.z + d.z) * s.z + ftanh(e.w + d.w) * s.w;
    }
    acc = warp_sum(acc);
    if (lane == 0) scores[w] = acc + bsc[0];
}

// ---------------- softmax over S + context = weights @ encoder_out ---------
__global__ void k_softctx(const float* __restrict__ scores, const float* __restrict__ eo,
                          float* __restrict__ ctx)
{
    __shared__ float w[SS];
    __shared__ float red[8];
    int b = blockIdx.x, tid = threadIdx.x;
    int lane = tid & 31, wid = tid >> 5;

    float sc = (tid < SS) ? scores[b * SS + tid] : -1e30f;
    float m = sc;
    #pragma unroll
    for (int o = 16; o; o >>= 1) m = fmaxf(m, __shfl_xor_sync(0xffffffffu, m, o));
    if (lane == 0) red[wid] = m;
    __syncthreads();
    float mx = red[0];
    #pragma unroll
    for (int i = 1; i < 8; i++) mx = fmaxf(mx, red[i]);

    float ex = (tid < SS) ? __expf(sc - mx) : 0.f;
    float s = ex;
    #pragma unroll
    for (int o = 16; o; o >>= 1) s += __shfl_xor_sync(0xffffffffu, s, o);
    __syncthreads();
    if (lane == 0) red[wid] = s;
    __syncthreads();
    float tot = 0.f;
    #pragma unroll
    for (int i = 0; i < 8; i++) tot += red[i];
    if (tid < SS) w[tid] = ex / tot;
    __syncthreads();

    const float* eb = eo + (size_t)b * SS * EE;
    for (int e = tid; e < EE; e += 256) {
        float a0 = 0.f, a1 = 0.f, a2 = 0.f, a3 = 0.f;
        #pragma unroll 4
        for (int s2 = 0; s2 < SS; s2 += 4) {
            a0 += w[s2 + 0] * eb[(s2 + 0) * EE + e];
            a1 += w[s2 + 1] * eb[(s2 + 1) * EE + e];
            a2 += w[s2 + 2] * eb[(s2 + 2) * EE + e];
            a3 += w[s2 + 3] * eb[(s2 + 3) * EE + e];
        }
        ctx[b * EE + e] = (a0 + a1) + (a2 + a3);
    }
}

// -------- per-step GEMM: [GC | GH] = [ctx|h](64x512) @ [W_ihE;W_hh]^T ------
__global__ __launch_bounds__(256)
void k_gcgh(const float* __restrict__ ctx, const float* __restrict__ h,
            const float* __restrict__ Wih, const float* __restrict__ Whh,
            float* __restrict__ gg)
{
    __shared__ float As[16][68];
    __shared__ float Bs[32][17];
    const int tid = threadIdx.x;
    const int lane = tid & 31, wid = tid >> 5;
    const int n0 = blockIdx.x * 32;

    const float* Am; const float* Bm; int ldbm; int nrow0;
    if (n0 < 1536) { Am = ctx; Bm = Wih + DD; ldbm = DD + EE; nrow0 = n0; }
    else           { Am = h;   Bm = Whh;      ldbm = HH;      nrow0 = n0 - 1536; }

    float acc[8];
    #pragma unroll
    for (int j = 0; j < 8; j++) acc[j] = 0.f;

    for (int k0 = 0; k0 < 512; k0 += 16) {
        {
            int row = tid >> 2, kq = tid & 3;
            float4 v = *(const float4*)(Am + row * 512 + k0 + kq * 4);
            As[kq * 4 + 0][row] = v.x; As[kq * 4 + 1][row] = v.y;
            As[kq * 4 + 2][row] = v.z; As[kq * 4 + 3][row] = v.w;
        }
        #pragma unroll
        for (int i = 0; i < 2; i++) {
            int linb = tid + i * 256;
            int nl = linb >> 4, kk = linb & 15;
            Bs[nl][kk] = Bm[(size_t)(nrow0 + nl) * ldbm + k0 + kk];
        }
        __syncthreads();
        #pragma unroll
        for (int k = 0; k < 16; k++) {
            float bv = Bs[lane][k];
            float4 a0 = *(const float4*)&As[k][wid * 8];
            float4 a1 = *(const float4*)&As[k][wid * 8 + 4];
            acc[0] += a0.x * bv; acc[1] += a0.y * bv;
            acc[2] += a0.z * bv; acc[3] += a0.w * bv;
            acc[4] += a1.x * bv; acc[5] += a1.y * bv;
            acc[6] += a1.z * bv; acc[7] += a1.w * bv;
        }
        __syncthreads();
    }
    #pragma unroll
    for (int j = 0; j < 8; j++)
        gg[(wid * 8 + j) * 3072 + n0 + lane] = acc[j];
}

// ---------------- GRU gate combine + hidden update ----------------
__global__ void k_gate(const float* __restrict__ gg, const float* __restrict__ giE,
                       const float* __restrict__ bhh, const float* __restrict__ hold,
                       float* __restrict__ hnew, float* __restrict__ Hbuf, int t)
{
    int idx = blockIdx.x * 256 + threadIdx.x;    // < 32768
    int b = idx >> 9, k = idx & 511;
    const float* g = gg + b * 3072;
    size_t mi = (size_t)(t * BB + b) * 1536;
    float r = fsig(giE[mi + k]        + g[k]        + g[1536 + k]        + bhh[k]);
    float z = fsig(giE[mi + 512 + k]  + g[512 + k]  + g[1536 + 512 + k]  + bhh[512 + k]);
    float n = ftanh(giE[mi + 1024 + k] + g[1024 + k]
                    + r * (g[1536 + 1024 + k] + bhh[1024 + k]));
    float ho = hold[idx];
    float hn = (1.f - z) * n + z * ho;
    hnew[idx] = hn;
    Hbuf[(size_t)(t * BB + b) * HH + k] = hn;
}

// ---------------- host driver ----------------
extern "C" void kernel_launch(void* const* d_in, const int* in_sizes, int n_in,
                              void* d_out, int out_size)
{
    const float* enc     = (const float*)d_in[0];
    const float* pooled  = (const float*)d_in[1];
    const int*   targets = (const int*)d_in[2];     // int32 on device (JAX x64 off)
    const float* emb     = (const float*)d_in[3];
    const float* W_enc   = (const float*)d_in[4];
    const float* b_enc   = (const float*)d_in[5];
    const float* W_dec   = (const float*)d_in[6];
    const float* b_dec   = (const float*)d_in[7];
    const float* W_score = (const float*)d_in[8];
    const float* b_score = (const float*)d_in[9];
    const float* W_ih    = (const float*)d_in[10];
    const float* W_hh    = (const float*)d_in[11];
    const float* b_ih    = (const float*)d_in[12];
    const float* b_hh    = (const float*)d_in[13];
    const float* W_out   = (const float*)d_in[14];
    const float* b_out   = (const float*)d_in[15];
    const float* W_init  = (const float*)d_in[16];
    const float* b_init  = (const float*)d_in[17];
    float* out = (float*)d_out;

    float *p_ep, *p_h0, *p_h1, *p_Hb, *p_dec, *p_sc, *p_ctx, *p_X, *p_giE, *p_gg;
    __nv_bfloat16 *p_Ae, *p_Be;
    cudaGetSymbolAddress((void**)&p_ep,  g_enc_proj);
    cudaGetSymbolAddress((void**)&p_h0,  g_h0buf);
    cudaGetSymbolAddress((void**)&p_h1,  g_h1buf);
    cudaGetSymbolAddress((void**)&p_Hb,  g_Hbuf);
    cudaGetSymbolAddress((void**)&p_dec, g_dec);
    cudaGetSymbolAddress((void**)&p_sc,  g_sc);
    cudaGetSymbolAddress((void**)&p_ctx, g_ctx);
    cudaGetSymbolAddress((void**)&p_X,   g_Xemb);
    cudaGetSymbolAddress((void**)&p_giE, g_giE);
    cudaGetSymbolAddress((void**)&p_gg,  g_gg);
    cudaGetSymbolAddress((void**)&p_Ae,  g_Ae);
    cudaGetSymbolAddress((void**)&p_Be,  g_Be);

    // split W_out into bf16 hi/lo (one-time per call; overlaps nothing but cheap)
    k_splitW<<<VV * 128 / 256, 256>>>(W_out, p_Be);
    // h0 = tanh(pooled @ W_init^T + b_init)
    gemm_tn<1><<<dim3(4, 1), 256>>>(pooled, W_init, p_h0, BB, HH, EE, EE, b_init);
    // enc_proj = encoder_out @ W_enc^T + b_enc          (12544 x 256 x 512)
    gemm_tn<0><<<dim3(2, 98), 256>>>(enc, W_enc, p_ep, BB * SS, AA, EE, EE, b_enc);
    // gather embeddings for all teacher-forced tokens
    k_gather<<<MM, 128>>>(targets, emb, p_X);
    // giE = Xemb @ W_ih[:, :D]^T + b_ih                 (1984 x 1536 x 512)
    gemm_tn<0><<<dim3(12, 16), 256>>>(p_X, W_ih, p_giE, MM, 3 * HH, DD,
                                      DD + EE, b_ih);

    for (int t = 0; t < LM1; t++) {
        float* hcur = (t & 1) ? p_h1 : p_h0;
        float* hnxt = (t & 1) ? p_h0 : p_h1;
        k_decproj<<<2048, 256>>>(hcur, W_dec, b_dec, p_dec);
        k_energy<<<1568, 256>>>(p_ep, p_dec, W_score, b_score, p_sc);
        k_softctx<<<BB, 256>>>(p_sc, enc, p_ctx);
        k_gcgh<<<96, 256>>>(p_ctx, hcur, W_ih, W_hh, p_gg);
        k_gate<<<128, 256>>>(p_gg, p_giE, b_hh, hcur, hnxt, p_Hb, t);
    }

    // split hidden states, then tensor-core logits GEMM
    k_splitA<<<MM * 128 / 256, 256>>>(p_Hb, p_Ae);
    k_bigmm<<<dim3(250, 16), 256>>>(p_Ae, p_Be, b_out, out);
}